// round 10
// baseline (speedup 1.0000x reference)
#include <cuda_runtime.h>
#include <cuda_bf16.h>
#include <stdint.h>

typedef unsigned long long ull;

#define BATCH 8
#define NPTS  8192
#define NPOINT 2048
#define NSAMP 32
#define PDIM  32
#define R2    0.25f

// ---------------- scratch (device globals; no allocations) ----------------
__device__ int   g_fps[BATCH * NPOINT];
__device__ __align__(16) float g_newxyz[BATCH * NPOINT * 3];
__device__ int   g_ball[BATCH * NPOINT * NSAMP];
__device__ __align__(256) float g_Q1[(size_t)BATCH * NPTS * 64];

// ---------------- packed f32x2 helpers ----------------
__device__ __forceinline__ ull pk(float lo, float hi) {
    ull r; asm("mov.b64 %0, {%1, %2};" : "=l"(r) : "f"(lo), "f"(hi)); return r;
}
__device__ __forceinline__ void upk(ull v, float& lo, float& hi) {
    asm("mov.b64 {%0, %1}, %2;" : "=f"(lo), "=f"(hi) : "l"(v));
}
__device__ __forceinline__ ull add2(ull a, ull b) {
    ull d; asm("add.rn.f32x2 %0, %1, %2;" : "=l"(d) : "l"(a), "l"(b)); return d;
}
__device__ __forceinline__ ull mul2(ull a, ull b) {
    ull d; asm("mul.rn.f32x2 %0, %1, %2;" : "=l"(d) : "l"(a), "l"(b)); return d;
}
__device__ __forceinline__ ull fma2(ull a, ull b, ull c) {
    ull d; asm("fma.rn.f32x2 %0, %1, %2, %3;" : "=l"(d) : "l"(a), "l"(b), "l"(c)); return d;
}
__device__ __forceinline__ ull umax64(ull a, ull b) { return a > b ? a : b; }

// ============================================================================
// 1) FPS: one block per batch. 512 thr x 16 pts in regs. ONE barrier/iter.
//    Per-warp key (wm<<32)|~nmin via redux.max + candidate scan + redux.min;
//    all threads max-tree the 16 keys. Two key banks, parity-alternated.
// ============================================================================
extern __shared__ float fsm[];   // sx[8192] sy[8192] sz[8192] | sKey[32] (ull)

__global__ void __launch_bounds__(512, 1) fps_kernel(const float* __restrict__ xyz) {
    float* sx = fsm;
    float* sy = fsm + NPTS;
    float* sz = fsm + 2 * NPTS;
    ull*   sKey = (ull*)(fsm + 3 * NPTS);      // 2 banks x 16 warps

    const int b = blockIdx.x;
    const int t = threadIdx.x;
    const int warp = t >> 5, lane = t & 31;
    const float* px = xyz + (size_t)b * 3 * NPTS;

    float dist[16];
    ull x2[8], y2[8], z2[8];
#pragma unroll
    for (int p = 0; p < 8; p++) {
        int n0 = t + (2 * p) * 512;
        int n1 = t + (2 * p + 1) * 512;
        float a0 = px[n0],            a1 = px[n1];
        float b0 = px[NPTS + n0],     b1 = px[NPTS + n1];
        float c0 = px[2 * NPTS + n0], c1 = px[2 * NPTS + n1];
        x2[p] = pk(a0, a1); y2[p] = pk(b0, b1); z2[p] = pk(c0, c1);
        sx[n0] = a0; sx[n1] = a1;
        sy[n0] = b0; sy[n1] = b1;
        sz[n0] = c0; sz[n1] = c1;
        dist[2 * p] = 1e10f; dist[2 * p + 1] = 1e10f;
    }
    if (t == 0) g_fps[b * NPOINT] = 0;
    __syncthreads();

    float cx = sx[0], cy = sy[0], cz = sz[0];
    int par = 0;

    for (int s = 0; s < NPOINT - 1; s++) {
        ull ncx = pk(-cx, -cx), ncy = pk(-cy, -cy), ncz = pk(-cz, -cz);
        float bdl = 0.0f;
#pragma unroll
        for (int p = 0; p < 8; p++) {
            ull dx = add2(x2[p], ncx);
            ull dy = add2(y2[p], ncy);
            ull dz = add2(z2[p], ncz);
            ull m = mul2(dx, dx); m = fma2(dy, dy, m); m = fma2(dz, dz, m);
            float d0, d1; upk(m, d0, d1);
            float t0 = fminf(dist[2 * p], d0);     dist[2 * p] = t0;
            float t1 = fminf(dist[2 * p + 1], d1); dist[2 * p + 1] = t1;
            bdl = fmaxf(bdl, fmaxf(t0, t1));
        }
        // warp max (dists >= 0: uint order == float order)
        unsigned wm = __reduce_max_sync(0xffffffffu, __float_as_uint(bdl));

        // candidate lanes find their min matching index; others report ~0
        unsigned n = 0xffffffffu;
        if (__float_as_uint(bdl) == wm) {
#pragma unroll
            for (int sl = 15; sl >= 0; sl--)
                if (__float_as_uint(dist[sl]) == wm) n = t + sl * 512;
        }
        unsigned nmin = __reduce_min_sync(0xffffffffu, n);
        if (lane == 0)
            sKey[par * 16 + warp] = ((ull)wm << 32) | (ull)(~nmin);
        __syncthreads();

        // every thread: max over 16 keys (max dist, then min index)
        const ulonglong2* kp = (const ulonglong2*)(sKey + par * 16);
        ulonglong2 k0 = kp[0], k1 = kp[1], k2 = kp[2], k3 = kp[3];
        ulonglong2 k4 = kp[4], k5 = kp[5], k6 = kp[6], k7 = kp[7];
        ull m0 = umax64(umax64(k0.x, k0.y), umax64(k1.x, k1.y));
        ull m1 = umax64(umax64(k2.x, k2.y), umax64(k3.x, k3.y));
        ull m2 = umax64(umax64(k4.x, k4.y), umax64(k5.x, k5.y));
        ull m3 = umax64(umax64(k6.x, k6.y), umax64(k7.x, k7.y));
        ull best = umax64(umax64(m0, m1), umax64(m2, m3));
        int win = (int)(~(unsigned)best);

        cx = sx[win]; cy = sy[win]; cz = sz[win];
        if (t == 0) g_fps[b * NPOINT + s + 1] = win;
        par ^= 1;
    }
}

// ============================================================================
// 2) Prep: gather centroid coords, write new_xyz output part
// ============================================================================
__global__ void prep_kernel(const float* __restrict__ xyz, float* __restrict__ out) {
    int i = blockIdx.x * 256 + threadIdx.x;              // 0..16383
    int b = i >> 11, sl = i & 2047;
    int f = g_fps[i];
    const float* px = xyz + (size_t)b * 3 * NPTS;
    float x = px[f], y = px[NPTS + f], z = px[2 * NPTS + f];
    g_newxyz[i * 3]     = x;
    g_newxyz[i * 3 + 1] = y;
    g_newxyz[i * 3 + 2] = z;
    out[(size_t)b * 3 * NPOINT + sl]              = x;
    out[(size_t)b * 3 * NPOINT + NPOINT + sl]     = y;
    out[(size_t)b * 3 * NPOINT + 2 * NPOINT + sl] = z;
}

// ============================================================================
// 3) Ball query: warp per centroid; 256-point groups, batched loads + 8 ballots
// ============================================================================
__global__ void __launch_bounds__(256, 4) ball_kernel(const float* __restrict__ xyz) {
    int warp = threadIdx.x >> 5, lane = threadIdx.x & 31;
    int gs = blockIdx.x * 8 + warp;                       // 0..16383
    int b = gs >> 11;
    const float* px = xyz + (size_t)b * 3 * NPTS;

    float cx = g_newxyz[gs * 3], cy = g_newxyz[gs * 3 + 1], cz = g_newxyz[gs * 3 + 2];
    float s2 = cx * cx + cy * cy + cz * cz;
    unsigned lmask = (1u << lane) - 1u;

    int cnt = 0;
    int firstIdx = 0;
    for (int base = 0; base < NPTS; base += 256) {
        float x[8], y[8], z[8];
#pragma unroll
        for (int c = 0; c < 8; c++) {
            int n = base + c * 32 + lane;
            x[c] = px[n]; y[c] = px[NPTS + n]; z[c] = px[2 * NPTS + n];
        }
        unsigned m[8];
#pragma unroll
        for (int c = 0; c < 8; c++) {
            float n2 = x[c] * x[c] + y[c] * y[c] + z[c] * z[c];
            float dot = x[c] * cx + y[c] * cy + z[c] * cz;
            float d = __fadd_rn(__fadd_rn(__fmul_rn(-2.0f, dot), s2), n2);
            m[c] = __ballot_sync(0xffffffffu, !(d > R2));
        }
#pragma unroll
        for (int c = 0; c < 8; c++) {
            unsigned mc = m[c];
            if (mc) {                                    // most groups are empty
                if (cnt == 0) firstIdx = base + c * 32 + __ffs(mc) - 1;
                int pos = cnt + __popc(mc & lmask);
                if (((mc >> lane) & 1u) && pos < NSAMP)
                    g_ball[(size_t)gs * NSAMP + pos] = base + c * 32 + lane;
                cnt += __popc(mc);
            }
        }
        if (cnt >= NSAMP) break;
    }
    if (cnt < NSAMP && lane >= cnt) g_ball[(size_t)gs * NSAMP + lane] = firstIdx;
}

// ============================================================================
// 4) Q1 = W1 * [xyz; pts] + b1 per SOURCE point (layer-1 hoist, 8x fewer MACs)
// ============================================================================
__global__ void __launch_bounds__(256, 4) q1_kernel(const float* __restrict__ xyz,
                                                    const float* __restrict__ pts,
                                                    const float* __restrict__ w1,
                                                    const float* __restrict__ b1) {
    __shared__ float sW[64 * 35];
    __shared__ float sB[64];
    __shared__ float sIn[4][35];
    int tid = threadIdx.x;
    for (int i = tid; i < 64 * 35; i += 256) sW[i] = w1[i];
    if (tid < 64) sB[tid] = b1[tid];
    int p0 = blockIdx.x * 4;
    for (int i = tid; i < 4 * 35; i += 256) {
        int p = i / 35, c = i % 35;
        int gp = p0 + p, bb = gp >> 13, n = gp & 8191;
        float v = (c < 3) ? xyz[((size_t)bb * 3 + c) * NPTS + n]
                          : pts[((size_t)bb * PDIM + (c - 3)) * NPTS + n];
        sIn[p][c] = v;
    }
    __syncthreads();
    int p = tid >> 6, o = tid & 63;
    float acc = sB[o];
#pragma unroll
    for (int c = 0; c < 35; c++) acc += sW[o * 35 + c] * sIn[p][c];
    g_Q1[(size_t)(p0 + p) * 64 + o] = acc;
}

// ============================================================================
// 5) MLP (layers 1-sub + 2 + 3) + maxpool. Warp per centroid, lane = sample.
// ============================================================================
#define SMF_W3  4096
#define SMF_B2  12288
#define SMF_B3  12352
#define SMF_W1C 12480
#define SMF_C1  12672
#define SMF_TOTAL (12672 + 512)      // floats

extern __shared__ float smf[];

__global__ void __launch_bounds__(256, 1) mlp_kernel(const float* __restrict__ w1,
                                                     const float* __restrict__ w2,
                                                     const float* __restrict__ b2,
                                                     const float* __restrict__ w3,
                                                     const float* __restrict__ b3,
                                                     float* __restrict__ out) {
    float* sW2  = smf;
    float* sW3  = smf + SMF_W3;
    float* sB2  = smf + SMF_B2;
    float* sB3  = smf + SMF_B3;
    float* sW1C = smf + SMF_W1C;
    float* sC1  = smf + SMF_C1;

    int tid = threadIdx.x;
    for (int i = tid; i < 4096; i += 256) sW2[i] = w2[i];
    for (int i = tid; i < 8192; i += 256) sW3[i] = w3[i];
    if (tid < 64)  sB2[tid] = b2[tid];
    if (tid < 128) sB3[tid] = b3[tid];
    if (tid < 192) sW1C[tid] = w1[(tid / 3) * 35 + (tid % 3)];
    __syncthreads();

    int warp = tid >> 5, lane = tid & 31;
    int gs = blockIdx.x * 8 + warp;                  // centroid id 0..16383
    int b = gs >> 11, sl = gs & 2047;

    float cx = g_newxyz[gs * 3], cy = g_newxyz[gs * 3 + 1], cz = g_newxyz[gs * 3 + 2];
    {
        int o = lane;
        sC1[warp * 64 + o] = sW1C[o * 3] * cx + sW1C[o * 3 + 1] * cy + sW1C[o * 3 + 2] * cz;
        o = lane + 32;
        sC1[warp * 64 + o] = sW1C[o * 3] * cx + sW1C[o * 3 + 1] * cy + sW1C[o * 3 + 2] * cz;
    }
    __syncwarp();

    int pidx = g_ball[(size_t)gs * NSAMP + lane];
    const float4* q  = (const float4*)(g_Q1 + (((size_t)b << 13) + pidx) * 64);
    const float4* c1 = (const float4*)(sC1 + warp * 64);

    // h1 = relu(Q1[idx] - C1), kept as packed pairs
    ull h1p[32];
#pragma unroll
    for (int j = 0; j < 16; j++) {
        float4 qv = q[j];
        float4 cv = c1[j];
        float a0 = fmaxf(qv.x - cv.x, 0.f);
        float a1 = fmaxf(qv.y - cv.y, 0.f);
        float a2 = fmaxf(qv.z - cv.z, 0.f);
        float a3 = fmaxf(qv.w - cv.w, 0.f);
        h1p[2 * j]     = pk(a0, a1);
        h1p[2 * j + 1] = pk(a2, a3);
    }

    // layer 2: h2 = relu(W2 h1 + b2), produced two outputs at a time
    ull h2p[32];
#pragma unroll
    for (int g = 0; g < 32; g++) {
        const ulonglong2* r0 = (const ulonglong2*)(sW2 + (2 * g) * 64);
        const ulonglong2* r1 = (const ulonglong2*)(sW2 + (2 * g + 1) * 64);
        ull a0 = 0, a1 = 0;
#pragma unroll
        for (int j = 0; j < 16; j++) {
            ulonglong2 wv0 = r0[j];
            a0 = fma2(wv0.x, h1p[2 * j], a0);
            a0 = fma2(wv0.y, h1p[2 * j + 1], a0);
            ulonglong2 wv1 = r1[j];
            a1 = fma2(wv1.x, h1p[2 * j], a1);
            a1 = fma2(wv1.y, h1p[2 * j + 1], a1);
        }
        float l0, h0, l1, h1v;
        upk(a0, l0, h0); upk(a1, l1, h1v);
        float v0 = fmaxf(l0 + h0 + sB2[2 * g], 0.f);
        float v1 = fmaxf(l1 + h1v + sB2[2 * g + 1], 0.f);
        h2p[g] = pk(v0, v1);
    }

    // layer 3 + maxpool over lanes (relu commutes with max)
    // unroll 4: interleaves 4 independent shfl reduction trees (SHFL lat 26)
    size_t obase = (size_t)BATCH * 3 * NPOINT + ((size_t)b * 128) * NPOINT + sl;
#pragma unroll 4
    for (int o3 = 0; o3 < 128; o3++) {
        const ulonglong2* r = (const ulonglong2*)(sW3 + o3 * 64);
        ull a0 = 0, a1 = 0;
#pragma unroll
        for (int j = 0; j < 8; j++) {
            ulonglong2 w0 = r[2 * j];
            ulonglong2 w1v = r[2 * j + 1];
            a0 = fma2(w0.x,  h2p[4 * j],     a0);
            a0 = fma2(w0.y,  h2p[4 * j + 1], a0);
            a1 = fma2(w1v.x, h2p[4 * j + 2], a1);
            a1 = fma2(w1v.y, h2p[4 * j + 3], a1);
        }
        float l0, h0, l1, h1v;
        upk(a0, l0, h0); upk(a1, l1, h1v);
        float v = (l0 + h0) + (l1 + h1v) + sB3[o3];
#pragma unroll
        for (int off = 16; off; off >>= 1)
            v = fmaxf(v, __shfl_xor_sync(0xffffffffu, v, off));
        v = fmaxf(v, 0.f);
        if (lane == (o3 & 31)) out[obase + (size_t)o3 * NPOINT] = v;
    }
}

// ============================================================================
extern "C" void kernel_launch(void* const* d_in, const int* in_sizes, int n_in,
                              void* d_out, int out_size) {
    const float* xyz = (const float*)d_in[0];
    const float* pts = (const float*)d_in[1];
    const float* w1  = (const float*)d_in[2];
    const float* b1  = (const float*)d_in[3];
    const float* w2  = (const float*)d_in[4];
    const float* b2  = (const float*)d_in[5];
    const float* w3  = (const float*)d_in[6];
    const float* b3  = (const float*)d_in[7];
    float* out = (float*)d_out;

    const int FPS_SMEM = (3 * NPTS) * sizeof(float) + 32 * sizeof(ull);

    static int smem_set = 0;
    if (!smem_set) {
        cudaFuncSetAttribute(mlp_kernel, cudaFuncAttributeMaxDynamicSharedMemorySize,
                             SMF_TOTAL * sizeof(float));
        cudaFuncSetAttribute(fps_kernel, cudaFuncAttributeMaxDynamicSharedMemorySize,
                             FPS_SMEM);
        smem_set = 1;
    }

    fps_kernel<<<BATCH, 512, FPS_SMEM>>>(xyz);
    q1_kernel<<<BATCH * NPTS / 4, 256>>>(xyz, pts, w1, b1);
    prep_kernel<<<BATCH * NPOINT / 256, 256>>>(xyz, out);
    ball_kernel<<<BATCH * NPOINT / 8, 256>>>(xyz);
    mlp_kernel<<<BATCH * NPOINT / 8, 256, SMF_TOTAL * sizeof(float)>>>(w1, w2, b2, w3, b3, out);
}

// round 12
// speedup vs baseline: 1.2488x; 1.2488x over previous
#include <cuda_runtime.h>
#include <cuda_bf16.h>
#include <stdint.h>

typedef unsigned long long ull;

#define BATCH 8
#define NPTS  8192
#define NPOINT 2048
#define NSAMP 32
#define PDIM  32
#define R2    0.25f

// ---------------- scratch (device globals; no allocations) ----------------
__device__ int   g_fps[BATCH * NPOINT];
__device__ __align__(16) float g_newxyz[BATCH * NPOINT * 3];
__device__ int   g_ball[BATCH * NPOINT * NSAMP];
__device__ __align__(256) float g_Q1[(size_t)BATCH * NPTS * 64];

// ---------------- packed f32x2 helpers ----------------
__device__ __forceinline__ ull pk(float lo, float hi) {
    ull r; asm("mov.b64 %0, {%1, %2};" : "=l"(r) : "f"(lo), "f"(hi)); return r;
}
__device__ __forceinline__ void upk(ull v, float& lo, float& hi) {
    asm("mov.b64 {%0, %1}, %2;" : "=f"(lo), "=f"(hi) : "l"(v));
}
__device__ __forceinline__ ull add2(ull a, ull b) {
    ull d; asm("add.rn.f32x2 %0, %1, %2;" : "=l"(d) : "l"(a), "l"(b)); return d;
}
__device__ __forceinline__ ull mul2(ull a, ull b) {
    ull d; asm("mul.rn.f32x2 %0, %1, %2;" : "=l"(d) : "l"(a), "l"(b)); return d;
}
__device__ __forceinline__ ull fma2(ull a, ull b, ull c) {
    ull d; asm("fma.rn.f32x2 %0, %1, %2, %3;" : "=l"(d) : "l"(a), "l"(b), "l"(c)); return d;
}

// ============================================================================
// 1) FPS: one block per batch. 512 thr x 16 pts in regs. redux.sync warp max,
//    block max from 16 smem partials (recomputed by all threads), rare
//    atomicMin first-occurrence argmax. (R5/R9 structure - best measured.)
// ============================================================================
extern __shared__ float fsm[];   // sx[8192] sy[8192] sz[8192] | sD[16] | sIdx[2]

__global__ void __launch_bounds__(512, 1) fps_kernel(const float* __restrict__ xyz) {
    float* sx = fsm;
    float* sy = fsm + NPTS;
    float* sz = fsm + 2 * NPTS;
    unsigned* sD   = (unsigned*)(fsm + 3 * NPTS);
    int*      sIdx = (int*)(sD + 16);

    const int b = blockIdx.x;
    const int t = threadIdx.x;
    const float* px = xyz + (size_t)b * 3 * NPTS;

    float dist[16];
    ull x2[8], y2[8], z2[8];
#pragma unroll
    for (int p = 0; p < 8; p++) {
        int n0 = t + (2 * p) * 512;
        int n1 = t + (2 * p + 1) * 512;
        float a0 = px[n0],            a1 = px[n1];
        float b0 = px[NPTS + n0],     b1 = px[NPTS + n1];
        float c0 = px[2 * NPTS + n0], c1 = px[2 * NPTS + n1];
        x2[p] = pk(a0, a1); y2[p] = pk(b0, b1); z2[p] = pk(c0, c1);
        sx[n0] = a0; sx[n1] = a1;
        sy[n0] = b0; sy[n1] = b1;
        sz[n0] = c0; sz[n1] = c1;
        dist[2 * p] = 1e10f; dist[2 * p + 1] = 1e10f;
    }
    if (t == 0) {
        g_fps[b * NPOINT] = 0;
        sIdx[0] = 0x7fffffff; sIdx[1] = 0x7fffffff;
    }
    __syncthreads();

    float cx = sx[0], cy = sy[0], cz = sz[0];
    int par = 0;

    for (int s = 0; s < NPOINT - 1; s++) {
        ull ncx = pk(-cx, -cx), ncy = pk(-cy, -cy), ncz = pk(-cz, -cz);
        float bdl = 0.0f;
#pragma unroll
        for (int p = 0; p < 8; p++) {
            ull dx = add2(x2[p], ncx);
            ull dy = add2(y2[p], ncy);
            ull dz = add2(z2[p], ncz);
            ull m = mul2(dx, dx); m = fma2(dy, dy, m); m = fma2(dz, dz, m);
            float d0, d1; upk(m, d0, d1);
            float t0 = fminf(dist[2 * p], d0);     dist[2 * p] = t0;
            float t1 = fminf(dist[2 * p + 1], d1); dist[2 * p + 1] = t1;
            bdl = fmaxf(bdl, fmaxf(t0, t1));
        }
        // warp max via redux (dists >= 0, uint order == float order)
        unsigned wm = __reduce_max_sync(0xffffffffu, __float_as_uint(bdl));
        if ((t & 31) == 0) sD[t >> 5] = wm;
        __syncthreads();

        // every thread computes the block max from the 16 partials (broadcast LDS)
        const uint4* pD = (const uint4*)sD;
        uint4 v0 = pD[0], v1 = pD[1], v2 = pD[2], v3 = pD[3];
        unsigned gm = max(max(max(v0.x, v0.y), max(v0.z, v0.w)),
                          max(max(v1.x, v1.y), max(v1.z, v1.w)));
        gm = max(gm, max(max(max(v2.x, v2.y), max(v2.z, v2.w)),
                         max(max(v3.x, v3.y), max(v3.z, v3.w))));
        float gmf = __uint_as_float(gm);

        // rare: candidate threads report their lowest matching index
        if (bdl == gmf) {
            int n = 0x7fffffff;
#pragma unroll
            for (int sl = 15; sl >= 0; sl--)
                if (dist[sl] == gmf) n = t + sl * 512;
            atomicMin(&sIdx[par], n);
        }
        __syncthreads();

        int win = sIdx[par];
        cx = sx[win]; cy = sy[win]; cz = sz[win];
        if (t == 0) {
            g_fps[b * NPOINT + s + 1] = win;
            sIdx[par ^ 1] = 0x7fffffff;   // ordered before next round's atomicMin by sync1
        }
        par ^= 1;
    }
}

// ============================================================================
// 2) Prep: gather centroid coords, write new_xyz output part
// ============================================================================
__global__ void prep_kernel(const float* __restrict__ xyz, float* __restrict__ out) {
    int i = blockIdx.x * 256 + threadIdx.x;              // 0..16383
    int b = i >> 11, sl = i & 2047;
    int f = g_fps[i];
    const float* px = xyz + (size_t)b * 3 * NPTS;
    float x = px[f], y = px[NPTS + f], z = px[2 * NPTS + f];
    g_newxyz[i * 3]     = x;
    g_newxyz[i * 3 + 1] = y;
    g_newxyz[i * 3 + 2] = z;
    out[(size_t)b * 3 * NPOINT + sl]              = x;
    out[(size_t)b * 3 * NPOINT + NPOINT + sl]     = y;
    out[(size_t)b * 3 * NPOINT + 2 * NPOINT + sl] = z;
}

// ============================================================================
// 3) Ball query: warp per centroid; 256-point groups, batched loads + 8 ballots
// ============================================================================
__global__ void __launch_bounds__(256, 4) ball_kernel(const float* __restrict__ xyz) {
    int warp = threadIdx.x >> 5, lane = threadIdx.x & 31;
    int gs = blockIdx.x * 8 + warp;                       // 0..16383
    int b = gs >> 11;
    const float* px = xyz + (size_t)b * 3 * NPTS;

    float cx = g_newxyz[gs * 3], cy = g_newxyz[gs * 3 + 1], cz = g_newxyz[gs * 3 + 2];
    float s2 = cx * cx + cy * cy + cz * cz;
    unsigned lmask = (1u << lane) - 1u;

    int cnt = 0;
    int firstIdx = 0;
    for (int base = 0; base < NPTS; base += 256) {
        float x[8], y[8], z[8];
#pragma unroll
        for (int c = 0; c < 8; c++) {
            int n = base + c * 32 + lane;
            x[c] = px[n]; y[c] = px[NPTS + n]; z[c] = px[2 * NPTS + n];
        }
        unsigned m[8];
#pragma unroll
        for (int c = 0; c < 8; c++) {
            float n2 = x[c] * x[c] + y[c] * y[c] + z[c] * z[c];
            float dot = x[c] * cx + y[c] * cy + z[c] * cz;
            float d = __fadd_rn(__fadd_rn(__fmul_rn(-2.0f, dot), s2), n2);
            m[c] = __ballot_sync(0xffffffffu, !(d > R2));
        }
#pragma unroll
        for (int c = 0; c < 8; c++) {
            unsigned mc = m[c];
            if (mc) {                                    // most groups are empty
                if (cnt == 0) firstIdx = base + c * 32 + __ffs(mc) - 1;
                int pos = cnt + __popc(mc & lmask);
                if (((mc >> lane) & 1u) && pos < NSAMP)
                    g_ball[(size_t)gs * NSAMP + pos] = base + c * 32 + lane;
                cnt += __popc(mc);
            }
        }
        if (cnt >= NSAMP) break;
    }
    if (cnt < NSAMP && lane >= cnt) g_ball[(size_t)gs * NSAMP + lane] = firstIdx;
}

// ============================================================================
// 4) Q1 = W1 * [xyz; pts] + b1 per SOURCE point (layer-1 hoist, 8x fewer MACs)
// ============================================================================
__global__ void __launch_bounds__(256, 4) q1_kernel(const float* __restrict__ xyz,
                                                    const float* __restrict__ pts,
                                                    const float* __restrict__ w1,
                                                    const float* __restrict__ b1) {
    __shared__ float sW[64 * 35];
    __shared__ float sB[64];
    __shared__ float sIn[4][35];
    int tid = threadIdx.x;
    for (int i = tid; i < 64 * 35; i += 256) sW[i] = w1[i];
    if (tid < 64) sB[tid] = b1[tid];
    int p0 = blockIdx.x * 4;
    for (int i = tid; i < 4 * 35; i += 256) {
        int p = i / 35, c = i % 35;
        int gp = p0 + p, bb = gp >> 13, n = gp & 8191;
        float v = (c < 3) ? xyz[((size_t)bb * 3 + c) * NPTS + n]
                          : pts[((size_t)bb * PDIM + (c - 3)) * NPTS + n];
        sIn[p][c] = v;
    }
    __syncthreads();
    int p = tid >> 6, o = tid & 63;
    float acc = sB[o];
#pragma unroll
    for (int c = 0; c < 35; c++) acc += sW[o * 35 + c] * sIn[p][c];
    g_Q1[(size_t)(p0 + p) * 64 + o] = acc;
}

// ============================================================================
// 5) MLP (layers 1-sub + 2 + 3) + maxpool. Warp per centroid, lane = sample.
// ============================================================================
#define SMF_W3  4096
#define SMF_B2  12288
#define SMF_B3  12352
#define SMF_W1C 12480
#define SMF_C1  12672
#define SMF_TOTAL (12672 + 512)      // floats

extern __shared__ float smf[];

__global__ void __launch_bounds__(256, 1) mlp_kernel(const float* __restrict__ w1,
                                                     const float* __restrict__ w2,
                                                     const float* __restrict__ b2,
                                                     const float* __restrict__ w3,
                                                     const float* __restrict__ b3,
                                                     float* __restrict__ out) {
    float* sW2  = smf;
    float* sW3  = smf + SMF_W3;
    float* sB2  = smf + SMF_B2;
    float* sB3  = smf + SMF_B3;
    float* sW1C = smf + SMF_W1C;
    float* sC1  = smf + SMF_C1;

    int tid = threadIdx.x;
    for (int i = tid; i < 4096; i += 256) sW2[i] = w2[i];
    for (int i = tid; i < 8192; i += 256) sW3[i] = w3[i];
    if (tid < 64)  sB2[tid] = b2[tid];
    if (tid < 128) sB3[tid] = b3[tid];
    if (tid < 192) sW1C[tid] = w1[(tid / 3) * 35 + (tid % 3)];
    __syncthreads();

    int warp = tid >> 5, lane = tid & 31;
    int gs = blockIdx.x * 8 + warp;                  // centroid id 0..16383
    int b = gs >> 11, sl = gs & 2047;

    float cx = g_newxyz[gs * 3], cy = g_newxyz[gs * 3 + 1], cz = g_newxyz[gs * 3 + 2];
    {
        int o = lane;
        sC1[warp * 64 + o] = sW1C[o * 3] * cx + sW1C[o * 3 + 1] * cy + sW1C[o * 3 + 2] * cz;
        o = lane + 32;
        sC1[warp * 64 + o] = sW1C[o * 3] * cx + sW1C[o * 3 + 1] * cy + sW1C[o * 3 + 2] * cz;
    }
    __syncwarp();

    int pidx = g_ball[(size_t)gs * NSAMP + lane];
    const float4* q  = (const float4*)(g_Q1 + (((size_t)b << 13) + pidx) * 64);
    const float4* c1 = (const float4*)(sC1 + warp * 64);

    // h1 = relu(Q1[idx] - C1), kept as packed pairs
    ull h1p[32];
#pragma unroll
    for (int j = 0; j < 16; j++) {
        float4 qv = q[j];
        float4 cv = c1[j];
        float a0 = fmaxf(qv.x - cv.x, 0.f);
        float a1 = fmaxf(qv.y - cv.y, 0.f);
        float a2 = fmaxf(qv.z - cv.z, 0.f);
        float a3 = fmaxf(qv.w - cv.w, 0.f);
        h1p[2 * j]     = pk(a0, a1);
        h1p[2 * j + 1] = pk(a2, a3);
    }

    // layer 2: h2 = relu(W2 h1 + b2), produced two outputs at a time
    ull h2p[32];
#pragma unroll
    for (int g = 0; g < 32; g++) {
        const ulonglong2* r0 = (const ulonglong2*)(sW2 + (2 * g) * 64);
        const ulonglong2* r1 = (const ulonglong2*)(sW2 + (2 * g + 1) * 64);
        ull a0 = 0, a1 = 0;
#pragma unroll
        for (int j = 0; j < 16; j++) {
            ulonglong2 wv0 = r0[j];
            a0 = fma2(wv0.x, h1p[2 * j], a0);
            a0 = fma2(wv0.y, h1p[2 * j + 1], a0);
            ulonglong2 wv1 = r1[j];
            a1 = fma2(wv1.x, h1p[2 * j], a1);
            a1 = fma2(wv1.y, h1p[2 * j + 1], a1);
        }
        float l0, h0, l1, h1v;
        upk(a0, l0, h0); upk(a1, l1, h1v);
        float v0 = fmaxf(l0 + h0 + sB2[2 * g], 0.f);
        float v1 = fmaxf(l1 + h1v + sB2[2 * g + 1], 0.f);
        h2p[g] = pk(v0, v1);
    }

    // layer 3 + maxpool over lanes (relu commutes with max)
    size_t obase = (size_t)BATCH * 3 * NPOINT + ((size_t)b * 128) * NPOINT + sl;
    for (int o3 = 0; o3 < 128; o3++) {
        const ulonglong2* r = (const ulonglong2*)(sW3 + o3 * 64);
        ull a0 = 0, a1 = 0;
#pragma unroll
        for (int j = 0; j < 8; j++) {
            ulonglong2 w0 = r[2 * j];
            ulonglong2 w1v = r[2 * j + 1];
            a0 = fma2(w0.x,  h2p[4 * j],     a0);
            a0 = fma2(w0.y,  h2p[4 * j + 1], a0);
            a1 = fma2(w1v.x, h2p[4 * j + 2], a1);
            a1 = fma2(w1v.y, h2p[4 * j + 3], a1);
        }
        float l0, h0, l1, h1v;
        upk(a0, l0, h0); upk(a1, l1, h1v);
        float v = (l0 + h0) + (l1 + h1v) + sB3[o3];
#pragma unroll
        for (int off = 16; off; off >>= 1)
            v = fmaxf(v, __shfl_xor_sync(0xffffffffu, v, off));
        v = fmaxf(v, 0.f);
        if (lane == (o3 & 31)) out[obase + (size_t)o3 * NPOINT] = v;
    }
}

// ============================================================================
extern "C" void kernel_launch(void* const* d_in, const int* in_sizes, int n_in,
                              void* d_out, int out_size) {
    const float* xyz = (const float*)d_in[0];
    const float* pts = (const float*)d_in[1];
    const float* w1  = (const float*)d_in[2];
    const float* b1  = (const float*)d_in[3];
    const float* w2  = (const float*)d_in[4];
    const float* b2  = (const float*)d_in[5];
    const float* w3  = (const float*)d_in[6];
    const float* b3  = (const float*)d_in[7];
    float* out = (float*)d_out;

    const int FPS_SMEM = (3 * NPTS) * sizeof(float) + 16 * sizeof(unsigned) + 2 * sizeof(int);

    static int smem_set = 0;
    if (!smem_set) {
        cudaFuncSetAttribute(mlp_kernel, cudaFuncAttributeMaxDynamicSharedMemorySize,
                             SMF_TOTAL * sizeof(float));
        cudaFuncSetAttribute(fps_kernel, cudaFuncAttributeMaxDynamicSharedMemorySize,
                             FPS_SMEM);
        smem_set = 1;
    }

    fps_kernel<<<BATCH, 512, FPS_SMEM>>>(xyz);
    q1_kernel<<<BATCH * NPTS / 4, 256>>>(xyz, pts, w1, b1);
    prep_kernel<<<BATCH * NPOINT / 256, 256>>>(xyz, out);
    ball_kernel<<<BATCH * NPOINT / 8, 256>>>(xyz);
    mlp_kernel<<<BATCH * NPOINT / 8, 256, SMF_TOTAL * sizeof(float)>>>(w1, w2, b2, w3, b3, out);
}

// round 13
// speedup vs baseline: 1.3669x; 1.0945x over previous
#include <cuda_runtime.h>
#include <cuda_bf16.h>
#include <stdint.h>

typedef unsigned long long ull;

#define BATCH 8
#define NPTS  8192
#define NPOINT 2048
#define NSAMP 32
#define PDIM  32
#define R2    0.25f

// ---------------- scratch (device globals; no allocations) ----------------
__device__ int   g_fps[BATCH * NPOINT];
__device__ __align__(16) float g_newxyz[BATCH * NPOINT * 3];
__device__ int   g_ball[BATCH * NPOINT * NSAMP];
__device__ __align__(256) float g_Q1[(size_t)BATCH * NPTS * 64];

// ---------------- packed f32x2 helpers ----------------
__device__ __forceinline__ ull pk(float lo, float hi) {
    ull r; asm("mov.b64 %0, {%1, %2};" : "=l"(r) : "f"(lo), "f"(hi)); return r;
}
__device__ __forceinline__ void upk(ull v, float& lo, float& hi) {
    asm("mov.b64 {%0, %1}, %2;" : "=f"(lo), "=f"(hi) : "l"(v));
}
__device__ __forceinline__ ull add2(ull a, ull b) {
    ull d; asm("add.rn.f32x2 %0, %1, %2;" : "=l"(d) : "l"(a), "l"(b)); return d;
}
__device__ __forceinline__ ull mul2(ull a, ull b) {
    ull d; asm("mul.rn.f32x2 %0, %1, %2;" : "=l"(d) : "l"(a), "l"(b)); return d;
}
__device__ __forceinline__ ull fma2(ull a, ull b, ull c) {
    ull d; asm("fma.rn.f32x2 %0, %1, %2, %3;" : "=l"(d) : "l"(a), "l"(b), "l"(c)); return d;
}

// ============================================================================
// 1) FPS: one block per batch. 512 thr x 16 pts in regs. redux.sync warp max,
//    block max from 16 smem partials (recomputed by all threads), rare
//    atomicMin first-occurrence argmax. (R5/R9 structure - best measured.)
// ============================================================================
extern __shared__ float fsm[];   // sx[8192] sy[8192] sz[8192] | sD[16] | sIdx[2]

__global__ void __launch_bounds__(512, 1) fps_kernel(const float* __restrict__ xyz) {
    float* sx = fsm;
    float* sy = fsm + NPTS;
    float* sz = fsm + 2 * NPTS;
    unsigned* sD   = (unsigned*)(fsm + 3 * NPTS);
    int*      sIdx = (int*)(sD + 16);

    const int b = blockIdx.x;
    const int t = threadIdx.x;
    const float* px = xyz + (size_t)b * 3 * NPTS;

    float dist[16];
    ull x2[8], y2[8], z2[8];
#pragma unroll
    for (int p = 0; p < 8; p++) {
        int n0 = t + (2 * p) * 512;
        int n1 = t + (2 * p + 1) * 512;
        float a0 = px[n0],            a1 = px[n1];
        float b0 = px[NPTS + n0],     b1 = px[NPTS + n1];
        float c0 = px[2 * NPTS + n0], c1 = px[2 * NPTS + n1];
        x2[p] = pk(a0, a1); y2[p] = pk(b0, b1); z2[p] = pk(c0, c1);
        sx[n0] = a0; sx[n1] = a1;
        sy[n0] = b0; sy[n1] = b1;
        sz[n0] = c0; sz[n1] = c1;
        dist[2 * p] = 1e10f; dist[2 * p + 1] = 1e10f;
    }
    if (t == 0) {
        g_fps[b * NPOINT] = 0;
        sIdx[0] = 0x7fffffff; sIdx[1] = 0x7fffffff;
    }
    __syncthreads();

    float cx = sx[0], cy = sy[0], cz = sz[0];
    int par = 0;

    for (int s = 0; s < NPOINT - 1; s++) {
        ull ncx = pk(-cx, -cx), ncy = pk(-cy, -cy), ncz = pk(-cz, -cz);
        float bdl = 0.0f;
#pragma unroll
        for (int p = 0; p < 8; p++) {
            ull dx = add2(x2[p], ncx);
            ull dy = add2(y2[p], ncy);
            ull dz = add2(z2[p], ncz);
            ull m = mul2(dx, dx); m = fma2(dy, dy, m); m = fma2(dz, dz, m);
            float d0, d1; upk(m, d0, d1);
            float t0 = fminf(dist[2 * p], d0);     dist[2 * p] = t0;
            float t1 = fminf(dist[2 * p + 1], d1); dist[2 * p + 1] = t1;
            bdl = fmaxf(bdl, fmaxf(t0, t1));
        }
        // warp max via redux (dists >= 0, uint order == float order)
        unsigned wm = __reduce_max_sync(0xffffffffu, __float_as_uint(bdl));
        if ((t & 31) == 0) sD[t >> 5] = wm;
        __syncthreads();

        // every thread computes the block max from the 16 partials (broadcast LDS)
        const uint4* pD = (const uint4*)sD;
        uint4 v0 = pD[0], v1 = pD[1], v2 = pD[2], v3 = pD[3];
        unsigned gm = max(max(max(v0.x, v0.y), max(v0.z, v0.w)),
                          max(max(v1.x, v1.y), max(v1.z, v1.w)));
        gm = max(gm, max(max(max(v2.x, v2.y), max(v2.z, v2.w)),
                         max(max(v3.x, v3.y), max(v3.z, v3.w))));
        float gmf = __uint_as_float(gm);

        // rare: candidate threads report their lowest matching index
        if (bdl == gmf) {
            int n = 0x7fffffff;
#pragma unroll
            for (int sl = 15; sl >= 0; sl--)
                if (dist[sl] == gmf) n = t + sl * 512;
            atomicMin(&sIdx[par], n);
        }
        __syncthreads();

        int win = sIdx[par];
        cx = sx[win]; cy = sy[win]; cz = sz[win];
        if (t == 0) {
            g_fps[b * NPOINT + s + 1] = win;
            sIdx[par ^ 1] = 0x7fffffff;   // ordered before next round's atomicMin by sync1
        }
        par ^= 1;
    }
}

// ============================================================================
// 2) Prep: gather centroid coords, write new_xyz output part
// ============================================================================
__global__ void prep_kernel(const float* __restrict__ xyz, float* __restrict__ out) {
    int i = blockIdx.x * 256 + threadIdx.x;              // 0..16383
    int b = i >> 11, sl = i & 2047;
    int f = g_fps[i];
    const float* px = xyz + (size_t)b * 3 * NPTS;
    float x = px[f], y = px[NPTS + f], z = px[2 * NPTS + f];
    g_newxyz[i * 3]     = x;
    g_newxyz[i * 3 + 1] = y;
    g_newxyz[i * 3 + 2] = z;
    out[(size_t)b * 3 * NPOINT + sl]              = x;
    out[(size_t)b * 3 * NPOINT + NPOINT + sl]     = y;
    out[(size_t)b * 3 * NPOINT + 2 * NPOINT + sl] = z;
}

// ============================================================================
// 3) Ball query: warp per centroid; 256-point groups, batched loads + 8 ballots
// ============================================================================
__global__ void __launch_bounds__(256, 4) ball_kernel(const float* __restrict__ xyz) {
    int warp = threadIdx.x >> 5, lane = threadIdx.x & 31;
    int gs = blockIdx.x * 8 + warp;                       // 0..16383
    int b = gs >> 11;
    const float* px = xyz + (size_t)b * 3 * NPTS;

    float cx = g_newxyz[gs * 3], cy = g_newxyz[gs * 3 + 1], cz = g_newxyz[gs * 3 + 2];
    float s2 = cx * cx + cy * cy + cz * cz;
    unsigned lmask = (1u << lane) - 1u;

    int cnt = 0;
    int firstIdx = 0;
    for (int base = 0; base < NPTS; base += 256) {
        float x[8], y[8], z[8];
#pragma unroll
        for (int c = 0; c < 8; c++) {
            int n = base + c * 32 + lane;
            x[c] = px[n]; y[c] = px[NPTS + n]; z[c] = px[2 * NPTS + n];
        }
        unsigned m[8];
#pragma unroll
        for (int c = 0; c < 8; c++) {
            float n2 = x[c] * x[c] + y[c] * y[c] + z[c] * z[c];
            float dot = x[c] * cx + y[c] * cy + z[c] * cz;
            float d = __fadd_rn(__fadd_rn(__fmul_rn(-2.0f, dot), s2), n2);
            m[c] = __ballot_sync(0xffffffffu, !(d > R2));
        }
#pragma unroll
        for (int c = 0; c < 8; c++) {
            unsigned mc = m[c];
            if (mc) {                                    // most groups are empty
                if (cnt == 0) firstIdx = base + c * 32 + __ffs(mc) - 1;
                int pos = cnt + __popc(mc & lmask);
                if (((mc >> lane) & 1u) && pos < NSAMP)
                    g_ball[(size_t)gs * NSAMP + pos] = base + c * 32 + lane;
                cnt += __popc(mc);
            }
        }
        if (cnt >= NSAMP) break;
    }
    if (cnt < NSAMP && lane >= cnt) g_ball[(size_t)gs * NSAMP + lane] = firstIdx;
}

// ============================================================================
// 4) Q1 = W1 * [xyz; pts] + b1 per SOURCE point (layer-1 hoist, 8x fewer MACs)
// ============================================================================
__global__ void __launch_bounds__(256, 4) q1_kernel(const float* __restrict__ xyz,
                                                    const float* __restrict__ pts,
                                                    const float* __restrict__ w1,
                                                    const float* __restrict__ b1) {
    __shared__ float sW[64 * 35];
    __shared__ float sB[64];
    __shared__ float sIn[4][35];
    int tid = threadIdx.x;
    for (int i = tid; i < 64 * 35; i += 256) sW[i] = w1[i];
    if (tid < 64) sB[tid] = b1[tid];
    int p0 = blockIdx.x * 4;
    for (int i = tid; i < 4 * 35; i += 256) {
        int p = i / 35, c = i % 35;
        int gp = p0 + p, bb = gp >> 13, n = gp & 8191;
        float v = (c < 3) ? xyz[((size_t)bb * 3 + c) * NPTS + n]
                          : pts[((size_t)bb * PDIM + (c - 3)) * NPTS + n];
        sIn[p][c] = v;
    }
    __syncthreads();
    int p = tid >> 6, o = tid & 63;
    float acc = sB[o];
#pragma unroll
    for (int c = 0; c < 35; c++) acc += sW[o * 35 + c] * sIn[p][c];
    g_Q1[(size_t)(p0 + p) * 64 + o] = acc;
}

// ============================================================================
// 5) MLP (layers 1-sub + 2 + 3) + maxpool. Warp per centroid, lane = sample.
// ============================================================================
#define SMF_W3  4096
#define SMF_B2  12288
#define SMF_B3  12352
#define SMF_W1C 12480
#define SMF_C1  12672
#define SMF_TOTAL (12672 + 512)      // floats

extern __shared__ float smf[];

__global__ void __launch_bounds__(256, 1) mlp_kernel(const float* __restrict__ w1,
                                                     const float* __restrict__ w2,
                                                     const float* __restrict__ b2,
                                                     const float* __restrict__ w3,
                                                     const float* __restrict__ b3,
                                                     float* __restrict__ out) {
    float* sW2  = smf;
    float* sW3  = smf + SMF_W3;
    float* sB2  = smf + SMF_B2;
    float* sB3  = smf + SMF_B3;
    float* sW1C = smf + SMF_W1C;
    float* sC1  = smf + SMF_C1;

    int tid = threadIdx.x;
    for (int i = tid; i < 4096; i += 256) sW2[i] = w2[i];
    for (int i = tid; i < 8192; i += 256) sW3[i] = w3[i];
    if (tid < 64)  sB2[tid] = b2[tid];
    if (tid < 128) sB3[tid] = b3[tid];
    if (tid < 192) sW1C[tid] = w1[(tid / 3) * 35 + (tid % 3)];
    __syncthreads();

    int warp = tid >> 5, lane = tid & 31;
    int gs = blockIdx.x * 8 + warp;                  // centroid id 0..16383
    int b = gs >> 11, sl = gs & 2047;

    float cx = g_newxyz[gs * 3], cy = g_newxyz[gs * 3 + 1], cz = g_newxyz[gs * 3 + 2];
    {
        int o = lane;
        sC1[warp * 64 + o] = sW1C[o * 3] * cx + sW1C[o * 3 + 1] * cy + sW1C[o * 3 + 2] * cz;
        o = lane + 32;
        sC1[warp * 64 + o] = sW1C[o * 3] * cx + sW1C[o * 3 + 1] * cy + sW1C[o * 3 + 2] * cz;
    }
    __syncwarp();

    int pidx = g_ball[(size_t)gs * NSAMP + lane];
    const float4* q  = (const float4*)(g_Q1 + (((size_t)b << 13) + pidx) * 64);
    const float4* c1 = (const float4*)(sC1 + warp * 64);

    // h1 = relu(Q1[idx] - C1), kept as packed pairs
    ull h1p[32];
#pragma unroll
    for (int j = 0; j < 16; j++) {
        float4 qv = q[j];
        float4 cv = c1[j];
        float a0 = fmaxf(qv.x - cv.x, 0.f);
        float a1 = fmaxf(qv.y - cv.y, 0.f);
        float a2 = fmaxf(qv.z - cv.z, 0.f);
        float a3 = fmaxf(qv.w - cv.w, 0.f);
        h1p[2 * j]     = pk(a0, a1);
        h1p[2 * j + 1] = pk(a2, a3);
    }

    // layer 2: h2 = relu(W2 h1 + b2), produced two outputs at a time
    ull h2p[32];
#pragma unroll
    for (int g = 0; g < 32; g++) {
        const ulonglong2* r0 = (const ulonglong2*)(sW2 + (2 * g) * 64);
        const ulonglong2* r1 = (const ulonglong2*)(sW2 + (2 * g + 1) * 64);
        ull a0 = 0, a1 = 0;
#pragma unroll
        for (int j = 0; j < 16; j++) {
            ulonglong2 wv0 = r0[j];
            a0 = fma2(wv0.x, h1p[2 * j], a0);
            a0 = fma2(wv0.y, h1p[2 * j + 1], a0);
            ulonglong2 wv1 = r1[j];
            a1 = fma2(wv1.x, h1p[2 * j], a1);
            a1 = fma2(wv1.y, h1p[2 * j + 1], a1);
        }
        float l0, h0, l1, h1v;
        upk(a0, l0, h0); upk(a1, l1, h1v);
        float v0 = fmaxf(l0 + h0 + sB2[2 * g], 0.f);
        float v1 = fmaxf(l1 + h1v + sB2[2 * g + 1], 0.f);
        h2p[g] = pk(v0, v1);
    }

    // layer 3 + maxpool over lanes. relu FIRST (commutes with max), so values
    // are nonneg and the 5-shfl tree becomes ONE redux.max on the bit pattern.
    size_t obase = (size_t)BATCH * 3 * NPOINT + ((size_t)b * 128) * NPOINT + sl;
    for (int o3 = 0; o3 < 128; o3++) {
        const ulonglong2* r = (const ulonglong2*)(sW3 + o3 * 64);
        ull a0 = 0, a1 = 0;
#pragma unroll
        for (int j = 0; j < 8; j++) {
            ulonglong2 w0 = r[2 * j];
            ulonglong2 w1v = r[2 * j + 1];
            a0 = fma2(w0.x,  h2p[4 * j],     a0);
            a0 = fma2(w0.y,  h2p[4 * j + 1], a0);
            a1 = fma2(w1v.x, h2p[4 * j + 2], a1);
            a1 = fma2(w1v.y, h2p[4 * j + 3], a1);
        }
        float l0, h0, l1, h1v;
        upk(a0, l0, h0); upk(a1, l1, h1v);
        float v = fmaxf((l0 + h0) + (l1 + h1v) + sB3[o3], 0.f);
        unsigned vm = __reduce_max_sync(0xffffffffu, __float_as_uint(v));
        if (lane == (o3 & 31)) out[obase + (size_t)o3 * NPOINT] = __uint_as_float(vm);
    }
}

// ============================================================================
extern "C" void kernel_launch(void* const* d_in, const int* in_sizes, int n_in,
                              void* d_out, int out_size) {
    const float* xyz = (const float*)d_in[0];
    const float* pts = (const float*)d_in[1];
    const float* w1  = (const float*)d_in[2];
    const float* b1  = (const float*)d_in[3];
    const float* w2  = (const float*)d_in[4];
    const float* b2  = (const float*)d_in[5];
    const float* w3  = (const float*)d_in[6];
    const float* b3  = (const float*)d_in[7];
    float* out = (float*)d_out;

    const int FPS_SMEM = (3 * NPTS) * sizeof(float) + 16 * sizeof(unsigned) + 2 * sizeof(int);

    static int smem_set = 0;
    if (!smem_set) {
        cudaFuncSetAttribute(mlp_kernel, cudaFuncAttributeMaxDynamicSharedMemorySize,
                             SMF_TOTAL * sizeof(float));
        cudaFuncSetAttribute(fps_kernel, cudaFuncAttributeMaxDynamicSharedMemorySize,
                             FPS_SMEM);
        smem_set = 1;
    }

    fps_kernel<<<BATCH, 512, FPS_SMEM>>>(xyz);
    q1_kernel<<<BATCH * NPTS / 4, 256>>>(xyz, pts, w1, b1);
    prep_kernel<<<BATCH * NPOINT / 256, 256>>>(xyz, out);
    ball_kernel<<<BATCH * NPOINT / 8, 256>>>(xyz);
    mlp_kernel<<<BATCH * NPOINT / 8, 256, SMF_TOTAL * sizeof(float)>>>(w1, w2, b2, w3, b3, out);
}

// round 14
// speedup vs baseline: 1.4215x; 1.0399x over previous
#include <cuda_runtime.h>
#include <cuda_bf16.h>
#include <stdint.h>

typedef unsigned long long ull;

#define BATCH 8
#define NPTS  8192
#define NPOINT 2048
#define NSAMP 32
#define PDIM  32
#define R2    0.25f

// ---------------- scratch (device globals; no allocations) ----------------
__device__ int   g_fps[BATCH * NPOINT];
__device__ int   g_prog[BATCH];                 // published fps progress per batch
__device__ __align__(16) float g_newxyz[BATCH * NPOINT * 3];
__device__ int   g_ball[BATCH * NPOINT * NSAMP];
__device__ __align__(256) float g_Q1[(size_t)BATCH * NPTS * 64];

// ---------------- packed f32x2 helpers ----------------
__device__ __forceinline__ ull pk(float lo, float hi) {
    ull r; asm("mov.b64 %0, {%1, %2};" : "=l"(r) : "f"(lo), "f"(hi)); return r;
}
__device__ __forceinline__ void upk(ull v, float& lo, float& hi) {
    asm("mov.b64 {%0, %1}, %2;" : "=f"(lo), "=f"(hi) : "l"(v));
}
__device__ __forceinline__ ull add2(ull a, ull b) {
    ull d; asm("add.rn.f32x2 %0, %1, %2;" : "=l"(d) : "l"(a), "l"(b)); return d;
}
__device__ __forceinline__ ull mul2(ull a, ull b) {
    ull d; asm("mul.rn.f32x2 %0, %1, %2;" : "=l"(d) : "l"(a), "l"(b)); return d;
}
__device__ __forceinline__ ull fma2(ull a, ull b, ull c) {
    ull d; asm("fma.rn.f32x2 %0, %1, %2, %3;" : "=l"(d) : "l"(a), "l"(b), "l"(c)); return d;
}
__device__ __forceinline__ void st_rel(int* p, int v) {
    asm volatile("st.release.gpu.global.b32 [%0], %1;" :: "l"(p), "r"(v) : "memory");
}
__device__ __forceinline__ int ld_acq(const int* p) {
    int v; asm volatile("ld.acquire.gpu.global.b32 %0, [%1];" : "=r"(v) : "l"(p) : "memory");
    return v;
}

// ============================================================================
// 1) FPS: one block per batch. 512 thr x 16 pts in regs. redux.sync warp max,
//    block max from 16 smem partials, rare atomicMin first-occurrence argmax.
//    Publishes progress (entries valid in g_fps) every 64 iters via st.release.
// ============================================================================
extern __shared__ float fsm[];   // sx[8192] sy[8192] sz[8192] | sD[16] | sIdx[2]

__global__ void __launch_bounds__(512, 1) fps_kernel(const float* __restrict__ xyz) {
    float* sx = fsm;
    float* sy = fsm + NPTS;
    float* sz = fsm + 2 * NPTS;
    unsigned* sD   = (unsigned*)(fsm + 3 * NPTS);
    int*      sIdx = (int*)(sD + 16);

    const int b = blockIdx.x;
    const int t = threadIdx.x;
    const float* px = xyz + (size_t)b * 3 * NPTS;

    float dist[16];
    ull x2[8], y2[8], z2[8];
#pragma unroll
    for (int p = 0; p < 8; p++) {
        int n0 = t + (2 * p) * 512;
        int n1 = t + (2 * p + 1) * 512;
        float a0 = px[n0],            a1 = px[n1];
        float b0 = px[NPTS + n0],     b1 = px[NPTS + n1];
        float c0 = px[2 * NPTS + n0], c1 = px[2 * NPTS + n1];
        x2[p] = pk(a0, a1); y2[p] = pk(b0, b1); z2[p] = pk(c0, c1);
        sx[n0] = a0; sx[n1] = a1;
        sy[n0] = b0; sy[n1] = b1;
        sz[n0] = c0; sz[n1] = c1;
        dist[2 * p] = 1e10f; dist[2 * p + 1] = 1e10f;
    }
    if (t == 0) {
        g_prog[b] = 0;                       // reset before any publish this run
        g_fps[b * NPOINT] = 0;
        sIdx[0] = 0x7fffffff; sIdx[1] = 0x7fffffff;
    }
    __syncthreads();

    float cx = sx[0], cy = sy[0], cz = sz[0];
    int par = 0;

    for (int s = 0; s < NPOINT - 1; s++) {
        ull ncx = pk(-cx, -cx), ncy = pk(-cy, -cy), ncz = pk(-cz, -cz);
        float bdl = 0.0f;
#pragma unroll
        for (int p = 0; p < 8; p++) {
            ull dx = add2(x2[p], ncx);
            ull dy = add2(y2[p], ncy);
            ull dz = add2(z2[p], ncz);
            ull m = mul2(dx, dx); m = fma2(dy, dy, m); m = fma2(dz, dz, m);
            float d0, d1; upk(m, d0, d1);
            float t0 = fminf(dist[2 * p], d0);     dist[2 * p] = t0;
            float t1 = fminf(dist[2 * p + 1], d1); dist[2 * p + 1] = t1;
            bdl = fmaxf(bdl, fmaxf(t0, t1));
        }
        // warp max via redux (dists >= 0, uint order == float order)
        unsigned wm = __reduce_max_sync(0xffffffffu, __float_as_uint(bdl));
        if ((t & 31) == 0) sD[t >> 5] = wm;
        __syncthreads();

        // every thread computes the block max from the 16 partials (broadcast LDS)
        const uint4* pD = (const uint4*)sD;
        uint4 v0 = pD[0], v1 = pD[1], v2 = pD[2], v3 = pD[3];
        unsigned gm = max(max(max(v0.x, v0.y), max(v0.z, v0.w)),
                          max(max(v1.x, v1.y), max(v1.z, v1.w)));
        gm = max(gm, max(max(max(v2.x, v2.y), max(v2.z, v2.w)),
                         max(max(v3.x, v3.y), max(v3.z, v3.w))));
        float gmf = __uint_as_float(gm);

        // rare: candidate threads report their lowest matching index
        if (bdl == gmf) {
            int n = 0x7fffffff;
#pragma unroll
            for (int sl = 15; sl >= 0; sl--)
                if (dist[sl] == gmf) n = t + sl * 512;
            atomicMin(&sIdx[par], n);
        }
        __syncthreads();

        int win = sIdx[par];
        cx = sx[win]; cy = sy[win]; cz = sz[win];
        if (t == 0) {
            g_fps[b * NPOINT + s + 1] = win;
            sIdx[par ^ 1] = 0x7fffffff;   // ordered before next round's atomicMin by sync1
            if ((s & 63) == 63) st_rel(&g_prog[b], s + 2);   // entries 0..s+1 valid
        }
        par ^= 1;
    }
    if (t == 0) st_rel(&g_prog[b], NPOINT);
}

// ============================================================================
// 2) pbm: prep + ball, overlapped with fps. 128 blocks x 8 warps; warp wg
//    handles centroids ord = k*1024 + wg (k=0..15), ord = sl*8 + b, so each
//    warp's wait points are 128 fps-iterations apart and the final sl range
//    is spread across 128 warps (small post-fps tail).
// ============================================================================
__global__ void __launch_bounds__(256, 4) pbm_kernel(const float* __restrict__ xyz,
                                                     float* __restrict__ out) {
    int warp = threadIdx.x >> 5, lane = threadIdx.x & 31;
    int wg = blockIdx.x * 8 + warp;                        // 0..1023
    unsigned lmask = (1u << lane) - 1u;

    for (int k = 0; k < 16; k++) {
        int ord = k * 1024 + wg;
        int b = ord & 7, sl = ord >> 3;
        int gs = b * 2048 + sl;
        const float* px = xyz + (size_t)b * 3 * NPTS;

        // wait until fps has produced entry sl for batch b (sleeping spin)
        while (ld_acq(&g_prog[b]) <= sl) __nanosleep(200);

        int f = g_fps[gs];
        float cx = px[f], cy = px[NPTS + f], cz = px[2 * NPTS + f];
        if (lane == 0) {
            g_newxyz[gs * 3]     = cx;
            g_newxyz[gs * 3 + 1] = cy;
            g_newxyz[gs * 3 + 2] = cz;
            out[(size_t)b * 3 * NPOINT + sl]              = cx;
            out[(size_t)b * 3 * NPOINT + NPOINT + sl]     = cy;
            out[(size_t)b * 3 * NPOINT + 2 * NPOINT + sl] = cz;
        }
        float s2 = cx * cx + cy * cy + cz * cz;

        int cnt = 0;
        int firstIdx = 0;
        for (int base = 0; base < NPTS; base += 256) {
            float x[8], y[8], z[8];
#pragma unroll
            for (int c = 0; c < 8; c++) {
                int n = base + c * 32 + lane;
                x[c] = px[n]; y[c] = px[NPTS + n]; z[c] = px[2 * NPTS + n];
            }
            unsigned m[8];
#pragma unroll
            for (int c = 0; c < 8; c++) {
                float n2 = x[c] * x[c] + y[c] * y[c] + z[c] * z[c];
                float dot = x[c] * cx + y[c] * cy + z[c] * cz;
                float d = __fadd_rn(__fadd_rn(__fmul_rn(-2.0f, dot), s2), n2);
                m[c] = __ballot_sync(0xffffffffu, !(d > R2));
            }
#pragma unroll
            for (int c = 0; c < 8; c++) {
                unsigned mc = m[c];
                if (mc) {
                    if (cnt == 0) firstIdx = base + c * 32 + __ffs(mc) - 1;
                    int pos = cnt + __popc(mc & lmask);
                    if (((mc >> lane) & 1u) && pos < NSAMP)
                        g_ball[(size_t)gs * NSAMP + pos] = base + c * 32 + lane;
                    cnt += __popc(mc);
                }
            }
            if (cnt >= NSAMP) break;
        }
        if (cnt < NSAMP && lane >= cnt) g_ball[(size_t)gs * NSAMP + lane] = firstIdx;
    }
}

// ============================================================================
// 3) Q1 = W1 * [xyz; pts] + b1 per SOURCE point (layer-1 hoist, 8x fewer MACs)
// ============================================================================
__global__ void __launch_bounds__(256, 4) q1_kernel(const float* __restrict__ xyz,
                                                    const float* __restrict__ pts,
                                                    const float* __restrict__ w1,
                                                    const float* __restrict__ b1) {
    __shared__ float sW[64 * 35];
    __shared__ float sB[64];
    __shared__ float sIn[4][35];
    int tid = threadIdx.x;
    for (int i = tid; i < 64 * 35; i += 256) sW[i] = w1[i];
    if (tid < 64) sB[tid] = b1[tid];
    int p0 = blockIdx.x * 4;
    for (int i = tid; i < 4 * 35; i += 256) {
        int p = i / 35, c = i % 35;
        int gp = p0 + p, bb = gp >> 13, n = gp & 8191;
        float v = (c < 3) ? xyz[((size_t)bb * 3 + c) * NPTS + n]
                          : pts[((size_t)bb * PDIM + (c - 3)) * NPTS + n];
        sIn[p][c] = v;
    }
    __syncthreads();
    int p = tid >> 6, o = tid & 63;
    float acc = sB[o];
#pragma unroll
    for (int c = 0; c < 35; c++) acc += sW[o * 35 + c] * sIn[p][c];
    g_Q1[(size_t)(p0 + p) * 64 + o] = acc;
}

// ============================================================================
// 4) MLP (layers 1-sub + 2 + 3) + maxpool. Warp per centroid, lane = sample.
// ============================================================================
#define SMF_W3  4096
#define SMF_B2  12288
#define SMF_B3  12352
#define SMF_W1C 12480
#define SMF_C1  12672
#define SMF_TOTAL (12672 + 512)      // floats

extern __shared__ float smf[];

__global__ void __launch_bounds__(256, 1) mlp_kernel(const float* __restrict__ w1,
                                                     const float* __restrict__ w2,
                                                     const float* __restrict__ b2,
                                                     const float* __restrict__ w3,
                                                     const float* __restrict__ b3,
                                                     float* __restrict__ out) {
    float* sW2  = smf;
    float* sW3  = smf + SMF_W3;
    float* sB2  = smf + SMF_B2;
    float* sB3  = smf + SMF_B3;
    float* sW1C = smf + SMF_W1C;
    float* sC1  = smf + SMF_C1;

    int tid = threadIdx.x;
    for (int i = tid; i < 4096; i += 256) sW2[i] = w2[i];
    for (int i = tid; i < 8192; i += 256) sW3[i] = w3[i];
    if (tid < 64)  sB2[tid] = b2[tid];
    if (tid < 128) sB3[tid] = b3[tid];
    if (tid < 192) sW1C[tid] = w1[(tid / 3) * 35 + (tid % 3)];
    __syncthreads();

    int warp = tid >> 5, lane = tid & 31;
    int gs = blockIdx.x * 8 + warp;                  // centroid id 0..16383
    int b = gs >> 11, sl = gs & 2047;

    float cx = g_newxyz[gs * 3], cy = g_newxyz[gs * 3 + 1], cz = g_newxyz[gs * 3 + 2];
    {
        int o = lane;
        sC1[warp * 64 + o] = sW1C[o * 3] * cx + sW1C[o * 3 + 1] * cy + sW1C[o * 3 + 2] * cz;
        o = lane + 32;
        sC1[warp * 64 + o] = sW1C[o * 3] * cx + sW1C[o * 3 + 1] * cy + sW1C[o * 3 + 2] * cz;
    }
    __syncwarp();

    int pidx = g_ball[(size_t)gs * NSAMP + lane];
    const float4* q  = (const float4*)(g_Q1 + (((size_t)b << 13) + pidx) * 64);
    const float4* c1 = (const float4*)(sC1 + warp * 64);

    // h1 = relu(Q1[idx] - C1), kept as packed pairs
    ull h1p[32];
#pragma unroll
    for (int j = 0; j < 16; j++) {
        float4 qv = q[j];
        float4 cv = c1[j];
        float a0 = fmaxf(qv.x - cv.x, 0.f);
        float a1 = fmaxf(qv.y - cv.y, 0.f);
        float a2 = fmaxf(qv.z - cv.z, 0.f);
        float a3 = fmaxf(qv.w - cv.w, 0.f);
        h1p[2 * j]     = pk(a0, a1);
        h1p[2 * j + 1] = pk(a2, a3);
    }

    // layer 2: h2 = relu(W2 h1 + b2), produced two outputs at a time
    ull h2p[32];
#pragma unroll
    for (int g = 0; g < 32; g++) {
        const ulonglong2* r0 = (const ulonglong2*)(sW2 + (2 * g) * 64);
        const ulonglong2* r1 = (const ulonglong2*)(sW2 + (2 * g + 1) * 64);
        ull a0 = 0, a1 = 0;
#pragma unroll
        for (int j = 0; j < 16; j++) {
            ulonglong2 wv0 = r0[j];
            a0 = fma2(wv0.x, h1p[2 * j], a0);
            a0 = fma2(wv0.y, h1p[2 * j + 1], a0);
            ulonglong2 wv1 = r1[j];
            a1 = fma2(wv1.x, h1p[2 * j], a1);
            a1 = fma2(wv1.y, h1p[2 * j + 1], a1);
        }
        float l0, h0, l1, h1v;
        upk(a0, l0, h0); upk(a1, l1, h1v);
        float v0 = fmaxf(l0 + h0 + sB2[2 * g], 0.f);
        float v1 = fmaxf(l1 + h1v + sB2[2 * g + 1], 0.f);
        h2p[g] = pk(v0, v1);
    }

    // layer 3 + maxpool over lanes. relu FIRST (commutes with max), so values
    // are nonneg and the 5-shfl tree becomes ONE redux.max on the bit pattern.
    size_t obase = (size_t)BATCH * 3 * NPOINT + ((size_t)b * 128) * NPOINT + sl;
    for (int o3 = 0; o3 < 128; o3++) {
        const ulonglong2* r = (const ulonglong2*)(sW3 + o3 * 64);
        ull a0 = 0, a1 = 0;
#pragma unroll
        for (int j = 0; j < 8; j++) {
            ulonglong2 w0 = r[2 * j];
            ulonglong2 w1v = r[2 * j + 1];
            a0 = fma2(w0.x,  h2p[4 * j],     a0);
            a0 = fma2(w0.y,  h2p[4 * j + 1], a0);
            a1 = fma2(w1v.x, h2p[4 * j + 2], a1);
            a1 = fma2(w1v.y, h2p[4 * j + 3], a1);
        }
        float l0, h0, l1, h1v;
        upk(a0, l0, h0); upk(a1, l1, h1v);
        float v = fmaxf((l0 + h0) + (l1 + h1v) + sB3[o3], 0.f);
        unsigned vm = __reduce_max_sync(0xffffffffu, __float_as_uint(v));
        if (lane == (o3 & 31)) out[obase + (size_t)o3 * NPOINT] = __uint_as_float(vm);
    }
}

// ============================================================================
extern "C" void kernel_launch(void* const* d_in, const int* in_sizes, int n_in,
                              void* d_out, int out_size) {
    const float* xyz = (const float*)d_in[0];
    const float* pts = (const float*)d_in[1];
    const float* w1  = (const float*)d_in[2];
    const float* b1  = (const float*)d_in[3];
    const float* w2  = (const float*)d_in[4];
    const float* b2  = (const float*)d_in[5];
    const float* w3  = (const float*)d_in[6];
    const float* b3  = (const float*)d_in[7];
    float* out = (float*)d_out;

    const int FPS_SMEM = (3 * NPTS) * sizeof(float) + 16 * sizeof(unsigned) + 2 * sizeof(int);

    static cudaStream_t s2 = nullptr;
    static cudaEvent_t eFork = nullptr, eJoin = nullptr;
    static int smem_set = 0;
    if (!smem_set) {
        cudaFuncSetAttribute(mlp_kernel, cudaFuncAttributeMaxDynamicSharedMemorySize,
                             SMF_TOTAL * sizeof(float));
        cudaFuncSetAttribute(fps_kernel, cudaFuncAttributeMaxDynamicSharedMemorySize,
                             FPS_SMEM);
        cudaStreamCreateWithFlags(&s2, cudaStreamNonBlocking);
        cudaEventCreateWithFlags(&eFork, cudaEventDisableTiming);
        cudaEventCreateWithFlags(&eJoin, cudaEventDisableTiming);
        smem_set = 1;
    }

    // fork side stream: q1 (independent) then pbm (consumes fps progress)
    cudaEventRecord(eFork, 0);
    cudaStreamWaitEvent(s2, eFork, 0);
    q1_kernel<<<BATCH * NPTS / 4, 256, 0, s2>>>(xyz, pts, w1, b1);
    pbm_kernel<<<128, 256, 0, s2>>>(xyz, out);
    cudaEventRecord(eJoin, s2);

    // main stream: fps runs concurrently with q1/pbm
    fps_kernel<<<BATCH, 512, FPS_SMEM>>>(xyz);

    // join, then mlp (needs g_newxyz, g_ball, g_Q1)
    cudaStreamWaitEvent(0, eJoin, 0);
    mlp_kernel<<<BATCH * NPOINT / 8, 256, SMF_TOTAL * sizeof(float)>>>(w1, w2, b2, w3, b3, out);
}

// round 15
// speedup vs baseline: 1.4775x; 1.0394x over previous
#include <cuda_runtime.h>
#include <cuda_bf16.h>
#include <stdint.h>

typedef unsigned long long ull;

#define BATCH 8
#define NPTS  8192
#define NPOINT 2048
#define NSAMP 32
#define PDIM  32
#define R2    0.25f

// ---------------- scratch (device globals; no allocations) ----------------
__device__ int   g_fps[BATCH * NPOINT];
__device__ int   g_prog[BATCH];
__device__ __align__(16) float g_newxyz[BATCH * NPOINT * 3];
__device__ int   g_ball[BATCH * NPOINT * NSAMP];
__device__ __align__(256) float g_Q1[(size_t)BATCH * NPTS * 64];
__device__ __align__(256) ull   g_H2[(size_t)BATCH * NPOINT * 32 * 32]; // [gs][g][k]

// ---------------- packed f32x2 helpers ----------------
__device__ __forceinline__ ull pk(float lo, float hi) {
    ull r; asm("mov.b64 %0, {%1, %2};" : "=l"(r) : "f"(lo), "f"(hi)); return r;
}
__device__ __forceinline__ void upk(ull v, float& lo, float& hi) {
    asm("mov.b64 {%0, %1}, %2;" : "=f"(lo), "=f"(hi) : "l"(v));
}
__device__ __forceinline__ ull add2(ull a, ull b) {
    ull d; asm("add.rn.f32x2 %0, %1, %2;" : "=l"(d) : "l"(a), "l"(b)); return d;
}
__device__ __forceinline__ ull mul2(ull a, ull b) {
    ull d; asm("mul.rn.f32x2 %0, %1, %2;" : "=l"(d) : "l"(a), "l"(b)); return d;
}
__device__ __forceinline__ ull fma2(ull a, ull b, ull c) {
    ull d; asm("fma.rn.f32x2 %0, %1, %2, %3;" : "=l"(d) : "l"(a), "l"(b), "l"(c)); return d;
}
__device__ __forceinline__ void st_rel(int* p, int v) {
    asm volatile("st.release.gpu.global.b32 [%0], %1;" :: "l"(p), "r"(v) : "memory");
}
__device__ __forceinline__ int ld_acq(const int* p) {
    int v; asm volatile("ld.acquire.gpu.global.b32 %0, [%1];" : "=r"(v) : "l"(p) : "memory");
    return v;
}

// ============================================================================
// 1) FPS (unchanged champion): 512 thr x 16 pts, redux warp max, atomicMin
//    argmax, progress published every 64 iters.
// ============================================================================
extern __shared__ float fsm[];

__global__ void __launch_bounds__(512, 1) fps_kernel(const float* __restrict__ xyz) {
    float* sx = fsm;
    float* sy = fsm + NPTS;
    float* sz = fsm + 2 * NPTS;
    unsigned* sD   = (unsigned*)(fsm + 3 * NPTS);
    int*      sIdx = (int*)(sD + 16);

    const int b = blockIdx.x;
    const int t = threadIdx.x;
    const float* px = xyz + (size_t)b * 3 * NPTS;

    float dist[16];
    ull x2[8], y2[8], z2[8];
#pragma unroll
    for (int p = 0; p < 8; p++) {
        int n0 = t + (2 * p) * 512;
        int n1 = t + (2 * p + 1) * 512;
        float a0 = px[n0],            a1 = px[n1];
        float b0 = px[NPTS + n0],     b1 = px[NPTS + n1];
        float c0 = px[2 * NPTS + n0], c1 = px[2 * NPTS + n1];
        x2[p] = pk(a0, a1); y2[p] = pk(b0, b1); z2[p] = pk(c0, c1);
        sx[n0] = a0; sx[n1] = a1;
        sy[n0] = b0; sy[n1] = b1;
        sz[n0] = c0; sz[n1] = c1;
        dist[2 * p] = 1e10f; dist[2 * p + 1] = 1e10f;
    }
    if (t == 0) {
        g_prog[b] = 0;
        g_fps[b * NPOINT] = 0;
        sIdx[0] = 0x7fffffff; sIdx[1] = 0x7fffffff;
    }
    __syncthreads();

    float cx = sx[0], cy = sy[0], cz = sz[0];
    int par = 0;

    for (int s = 0; s < NPOINT - 1; s++) {
        ull ncx = pk(-cx, -cx), ncy = pk(-cy, -cy), ncz = pk(-cz, -cz);
        float bdl = 0.0f;
#pragma unroll
        for (int p = 0; p < 8; p++) {
            ull dx = add2(x2[p], ncx);
            ull dy = add2(y2[p], ncy);
            ull dz = add2(z2[p], ncz);
            ull m = mul2(dx, dx); m = fma2(dy, dy, m); m = fma2(dz, dz, m);
            float d0, d1; upk(m, d0, d1);
            float t0 = fminf(dist[2 * p], d0);     dist[2 * p] = t0;
            float t1 = fminf(dist[2 * p + 1], d1); dist[2 * p + 1] = t1;
            bdl = fmaxf(bdl, fmaxf(t0, t1));
        }
        unsigned wm = __reduce_max_sync(0xffffffffu, __float_as_uint(bdl));
        if ((t & 31) == 0) sD[t >> 5] = wm;
        __syncthreads();

        const uint4* pD = (const uint4*)sD;
        uint4 v0 = pD[0], v1 = pD[1], v2 = pD[2], v3 = pD[3];
        unsigned gm = max(max(max(v0.x, v0.y), max(v0.z, v0.w)),
                          max(max(v1.x, v1.y), max(v1.z, v1.w)));
        gm = max(gm, max(max(max(v2.x, v2.y), max(v2.z, v2.w)),
                         max(max(v3.x, v3.y), max(v3.z, v3.w))));
        float gmf = __uint_as_float(gm);

        if (bdl == gmf) {
            int n = 0x7fffffff;
#pragma unroll
            for (int sl = 15; sl >= 0; sl--)
                if (dist[sl] == gmf) n = t + sl * 512;
            atomicMin(&sIdx[par], n);
        }
        __syncthreads();

        int win = sIdx[par];
        cx = sx[win]; cy = sy[win]; cz = sz[win];
        if (t == 0) {
            g_fps[b * NPOINT + s + 1] = win;
            sIdx[par ^ 1] = 0x7fffffff;
            if ((s & 63) == 63) st_rel(&g_prog[b], s + 2);
        }
        par ^= 1;
    }
    if (t == 0) st_rel(&g_prog[b], NPOINT);
}

// ============================================================================
// 2) pbm: prep + ball overlapped with fps (unchanged).
// ============================================================================
__global__ void __launch_bounds__(256, 4) pbm_kernel(const float* __restrict__ xyz,
                                                     float* __restrict__ out) {
    int warp = threadIdx.x >> 5, lane = threadIdx.x & 31;
    int wg = blockIdx.x * 8 + warp;
    unsigned lmask = (1u << lane) - 1u;

    for (int k = 0; k < 16; k++) {
        int ord = k * 1024 + wg;
        int b = ord & 7, sl = ord >> 3;
        int gs = b * 2048 + sl;
        const float* px = xyz + (size_t)b * 3 * NPTS;

        while (ld_acq(&g_prog[b]) <= sl) __nanosleep(200);

        int f = g_fps[gs];
        float cx = px[f], cy = px[NPTS + f], cz = px[2 * NPTS + f];
        if (lane == 0) {
            g_newxyz[gs * 3]     = cx;
            g_newxyz[gs * 3 + 1] = cy;
            g_newxyz[gs * 3 + 2] = cz;
            out[(size_t)b * 3 * NPOINT + sl]              = cx;
            out[(size_t)b * 3 * NPOINT + NPOINT + sl]     = cy;
            out[(size_t)b * 3 * NPOINT + 2 * NPOINT + sl] = cz;
        }
        float s2 = cx * cx + cy * cy + cz * cz;

        int cnt = 0;
        int firstIdx = 0;
        for (int base = 0; base < NPTS; base += 256) {
            float x[8], y[8], z[8];
#pragma unroll
            for (int c = 0; c < 8; c++) {
                int n = base + c * 32 + lane;
                x[c] = px[n]; y[c] = px[NPTS + n]; z[c] = px[2 * NPTS + n];
            }
            unsigned m[8];
#pragma unroll
            for (int c = 0; c < 8; c++) {
                float n2 = x[c] * x[c] + y[c] * y[c] + z[c] * z[c];
                float dot = x[c] * cx + y[c] * cy + z[c] * cz;
                float d = __fadd_rn(__fadd_rn(__fmul_rn(-2.0f, dot), s2), n2);
                m[c] = __ballot_sync(0xffffffffu, !(d > R2));
            }
#pragma unroll
            for (int c = 0; c < 8; c++) {
                unsigned mc = m[c];
                if (mc) {
                    if (cnt == 0) firstIdx = base + c * 32 + __ffs(mc) - 1;
                    int pos = cnt + __popc(mc & lmask);
                    if (((mc >> lane) & 1u) && pos < NSAMP)
                        g_ball[(size_t)gs * NSAMP + pos] = base + c * 32 + lane;
                    cnt += __popc(mc);
                }
            }
            if (cnt >= NSAMP) break;
        }
        if (cnt < NSAMP && lane >= cnt) g_ball[(size_t)gs * NSAMP + lane] = firstIdx;
    }
}

// ============================================================================
// 3) Q1 per source point (unchanged)
// ============================================================================
__global__ void __launch_bounds__(256, 4) q1_kernel(const float* __restrict__ xyz,
                                                    const float* __restrict__ pts,
                                                    const float* __restrict__ w1,
                                                    const float* __restrict__ b1) {
    __shared__ float sW[64 * 35];
    __shared__ float sB[64];
    __shared__ float sIn[4][35];
    int tid = threadIdx.x;
    for (int i = tid; i < 64 * 35; i += 256) sW[i] = w1[i];
    if (tid < 64) sB[tid] = b1[tid];
    int p0 = blockIdx.x * 4;
    for (int i = tid; i < 4 * 35; i += 256) {
        int p = i / 35, c = i % 35;
        int gp = p0 + p, bb = gp >> 13, n = gp & 8191;
        float v = (c < 3) ? xyz[((size_t)bb * 3 + c) * NPTS + n]
                          : pts[((size_t)bb * PDIM + (c - 3)) * NPTS + n];
        sIn[p][c] = v;
    }
    __syncthreads();
    int p = tid >> 6, o = tid & 63;
    float acc = sB[o];
#pragma unroll
    for (int c = 0; c < 35; c++) acc += sW[o * 35 + c] * sIn[p][c];
    g_Q1[(size_t)(p0 + p) * 64 + o] = acc;
}

// ============================================================================
// 4) mlp2: layer1-sub + layer2 -> g_H2. Warp per centroid, 2 CTAs/SM.
// ============================================================================
__global__ void __launch_bounds__(256, 2) mlp2_kernel(const float* __restrict__ w1,
                                                      const float* __restrict__ w2,
                                                      const float* __restrict__ b2) {
    __shared__ float sW2[4096];
    __shared__ float sB2[64];
    __shared__ float sW1C[192];
    __shared__ float sC1[8 * 64];

    int tid = threadIdx.x;
    for (int i = tid; i < 4096; i += 256) sW2[i] = w2[i];
    if (tid < 64)  sB2[tid] = b2[tid];
    if (tid < 192) sW1C[tid] = w1[(tid / 3) * 35 + (tid % 3)];
    __syncthreads();

    int warp = tid >> 5, lane = tid & 31;
    int gs = blockIdx.x * 8 + warp;
    int b = gs >> 11;

    float cx = g_newxyz[gs * 3], cy = g_newxyz[gs * 3 + 1], cz = g_newxyz[gs * 3 + 2];
    {
        int o = lane;
        sC1[warp * 64 + o] = sW1C[o * 3] * cx + sW1C[o * 3 + 1] * cy + sW1C[o * 3 + 2] * cz;
        o = lane + 32;
        sC1[warp * 64 + o] = sW1C[o * 3] * cx + sW1C[o * 3 + 1] * cy + sW1C[o * 3 + 2] * cz;
    }
    __syncwarp();

    int pidx = g_ball[(size_t)gs * NSAMP + lane];
    const float4* q  = (const float4*)(g_Q1 + (((size_t)b << 13) + pidx) * 64);
    const float4* c1 = (const float4*)(sC1 + warp * 64);

    ull h1p[32];
#pragma unroll
    for (int j = 0; j < 16; j++) {
        float4 qv = q[j];
        float4 cv = c1[j];
        float a0 = fmaxf(qv.x - cv.x, 0.f);
        float a1 = fmaxf(qv.y - cv.y, 0.f);
        float a2 = fmaxf(qv.z - cv.z, 0.f);
        float a3 = fmaxf(qv.w - cv.w, 0.f);
        h1p[2 * j]     = pk(a0, a1);
        h1p[2 * j + 1] = pk(a2, a3);
    }

    ull* h2out = g_H2 + ((size_t)gs * 32) * 32 + lane;
#pragma unroll
    for (int g = 0; g < 32; g++) {
        const ulonglong2* r0 = (const ulonglong2*)(sW2 + (2 * g) * 64);
        const ulonglong2* r1 = (const ulonglong2*)(sW2 + (2 * g + 1) * 64);
        ull a0 = 0, a1 = 0;
#pragma unroll
        for (int j = 0; j < 16; j++) {
            ulonglong2 wv0 = r0[j];
            a0 = fma2(wv0.x, h1p[2 * j], a0);
            a0 = fma2(wv0.y, h1p[2 * j + 1], a0);
            ulonglong2 wv1 = r1[j];
            a1 = fma2(wv1.x, h1p[2 * j], a1);
            a1 = fma2(wv1.y, h1p[2 * j + 1], a1);
        }
        float l0, h0, l1, h1v;
        upk(a0, l0, h0); upk(a1, l1, h1v);
        float v0 = fmaxf(l0 + h0 + sB2[2 * g], 0.f);
        float v1 = fmaxf(l1 + h1v + sB2[2 * g + 1], 0.f);
        h2out[(size_t)g * 32] = pk(v0, v1);
    }
}

// ============================================================================
// 5) mlp3: layer3 + maxpool. Warp handles TWO centroids (W3 stream shared).
//    128-thread blocks, 2 CTAs/SM budget.
// ============================================================================
__global__ void __launch_bounds__(128, 2) mlp3_kernel(const float* __restrict__ w3,
                                                      const float* __restrict__ b3,
                                                      float* __restrict__ out) {
    __shared__ float sW3[8192];
    __shared__ float sB3[128];

    int tid = threadIdx.x;
    for (int i = tid; i < 8192; i += 128) sW3[i] = w3[i];
    if (tid < 128) sB3[tid] = b3[tid];
    __syncthreads();

    int warp = tid >> 5, lane = tid & 31;
    int gw = blockIdx.x * 4 + warp;            // 0..8191
    int gsA = gw, gsB = gw + 8192;
    int bA = gsA >> 11, slA = gsA & 2047;
    int bB = gsB >> 11, slB = gsB & 2047;

    // load h2 for both centroids into registers (coalesced 256B per g)
    ull h2A[32], h2B[32];
    const ull* pA = g_H2 + ((size_t)gsA * 32) * 32 + lane;
    const ull* pB = g_H2 + ((size_t)gsB * 32) * 32 + lane;
#pragma unroll
    for (int g = 0; g < 32; g++) {
        h2A[g] = pA[(size_t)g * 32];
        h2B[g] = pB[(size_t)g * 32];
    }

    size_t obaseA = (size_t)BATCH * 3 * NPOINT + ((size_t)bA * 128) * NPOINT + slA;
    size_t obaseB = (size_t)BATCH * 3 * NPOINT + ((size_t)bB * 128) * NPOINT + slB;

    for (int o3 = 0; o3 < 128; o3++) {
        const ulonglong2* r = (const ulonglong2*)(sW3 + o3 * 64);
        ull a0 = 0, a1 = 0, c0 = 0, c1 = 0;
#pragma unroll
        for (int j = 0; j < 8; j++) {
            ulonglong2 w0 = r[2 * j];
            ulonglong2 w1v = r[2 * j + 1];
            a0 = fma2(w0.x,  h2A[4 * j],     a0);
            a0 = fma2(w0.y,  h2A[4 * j + 1], a0);
            a1 = fma2(w1v.x, h2A[4 * j + 2], a1);
            a1 = fma2(w1v.y, h2A[4 * j + 3], a1);
            c0 = fma2(w0.x,  h2B[4 * j],     c0);
            c0 = fma2(w0.y,  h2B[4 * j + 1], c0);
            c1 = fma2(w1v.x, h2B[4 * j + 2], c1);
            c1 = fma2(w1v.y, h2B[4 * j + 3], c1);
        }
        float l0, h0, l1, h1v;
        upk(a0, l0, h0); upk(a1, l1, h1v);
        float vA = fmaxf((l0 + h0) + (l1 + h1v) + sB3[o3], 0.f);
        upk(c0, l0, h0); upk(c1, l1, h1v);
        float vB = fmaxf((l0 + h0) + (l1 + h1v) + sB3[o3], 0.f);
        unsigned mA = __reduce_max_sync(0xffffffffu, __float_as_uint(vA));
        unsigned mB = __reduce_max_sync(0xffffffffu, __float_as_uint(vB));
        if (lane == (o3 & 31)) {
            out[obaseA + (size_t)o3 * NPOINT] = __uint_as_float(mA);
            out[obaseB + (size_t)o3 * NPOINT] = __uint_as_float(mB);
        }
    }
}

// ============================================================================
extern "C" void kernel_launch(void* const* d_in, const int* in_sizes, int n_in,
                              void* d_out, int out_size) {
    const float* xyz = (const float*)d_in[0];
    const float* pts = (const float*)d_in[1];
    const float* w1  = (const float*)d_in[2];
    const float* b1  = (const float*)d_in[3];
    const float* w2  = (const float*)d_in[4];
    const float* b2  = (const float*)d_in[5];
    const float* w3  = (const float*)d_in[6];
    const float* b3  = (const float*)d_in[7];
    float* out = (float*)d_out;

    const int FPS_SMEM = (3 * NPTS) * sizeof(float) + 16 * sizeof(unsigned) + 2 * sizeof(int);

    static cudaStream_t s2 = nullptr;
    static cudaEvent_t eFork = nullptr, eJoin = nullptr;
    static int smem_set = 0;
    if (!smem_set) {
        cudaFuncSetAttribute(fps_kernel, cudaFuncAttributeMaxDynamicSharedMemorySize,
                             FPS_SMEM);
        cudaStreamCreateWithFlags(&s2, cudaStreamNonBlocking);
        cudaEventCreateWithFlags(&eFork, cudaEventDisableTiming);
        cudaEventCreateWithFlags(&eJoin, cudaEventDisableTiming);
        smem_set = 1;
    }

    // fork side stream: q1 (independent) then pbm (consumes fps progress)
    cudaEventRecord(eFork, 0);
    cudaStreamWaitEvent(s2, eFork, 0);
    q1_kernel<<<BATCH * NPTS / 4, 256, 0, s2>>>(xyz, pts, w1, b1);
    pbm_kernel<<<128, 256, 0, s2>>>(xyz, out);
    cudaEventRecord(eJoin, s2);

    // main stream: fps runs concurrently with q1/pbm
    fps_kernel<<<BATCH, 512, FPS_SMEM>>>(xyz);

    // join, then split MLP
    cudaStreamWaitEvent(0, eJoin, 0);
    mlp2_kernel<<<BATCH * NPOINT / 8, 256>>>(w1, w2, b2);
    mlp3_kernel<<<BATCH * NPOINT / 8, 128>>>(w3, b3, out);
}